// round 11
// baseline (speedup 1.0000x reference)
#include <cuda_runtime.h>

#define TT 256
#define CC 195
#define HH 8
#define JJ 24            // q(8)|k(8)|v(8) per channel
#define NT 128           // threads per CTA; thread r owns rows 2r, 2r+1
#define CHUNK 8
#define NCHUNK 24        // 24*8 = 192; remainder 3 via direct LDG
#define XWS 68           // floats per channel in warp buffer (STS banks 4*lcol+lrow: conflict-free)
#define WF (CC * JJ)     // 4680 floats
#define XBW (CHUNK * XWS)  // 544 floats per warp buffer

typedef unsigned long long u64;

__device__ __forceinline__ u64 pack2(float v) {
    u64 r; asm("mov.b64 %0, {%1, %1};" : "=l"(r) : "f"(v)); return r;
}
__device__ __forceinline__ void unpack2(u64 v, float& lo, float& hi) {
    asm("mov.b64 {%0, %1}, %2;" : "=f"(lo), "=f"(hi) : "l"(v));
}
__device__ __forceinline__ void ffma2(u64& d, u64 a, u64 b) {
    asm("fma.rn.f32x2 %0, %1, %2, %0;" : "+l"(d) : "l"(a), "l"(b));
}
__device__ __forceinline__ u64 mul2(u64 a, u64 b) {
    u64 r; asm("mul.rn.f32x2 %0, %1, %2;" : "=l"(r) : "l"(a), "l"(b)); return r;
}

__global__ __launch_bounds__(NT, 5)
void head_attn_kernel(const float* __restrict__ x,
                      const float* __restrict__ Wq,
                      const float* __restrict__ Wk,
                      const float* __restrict__ Wv,
                      float* __restrict__ out)
{
    // phase A: [ w_s (18720B) | 4 x warp-private xbuf (2176B each) ] = 27424B
    // phase B: [ k_s (8KB) | v_s (8KB) ] overlays w_s region
    __shared__ __align__(16) float smem[WF + 4 * XBW];
    float* w_s = smem;

    const int tid = threadIdx.x;
    const int b   = blockIdx.x;
    const int w   = tid >> 5;
    const int l   = tid & 31;
    const int lcol = l & 7;      // staging channel within chunk
    const int lrow = l >> 3;     // staging row group 0..3
    float* xbuf = smem + WF + w * XBW;   // warp-private

    // ---- stage W as [c][24] (96B per c-slice, 16B-aligned) ----
    for (int i = tid; i < CC * HH; i += NT) {
        int c = i >> 3, h = i & 7;
        w_s[c * JJ +      h] = Wq[i];
        w_s[c * JJ +  8 + h] = Wk[i];
        w_s[c * JJ + 16 + h] = Wv[i];
    }

    // warp covers rows 64w..64w+63; staging lane handles rows lrow+4p, channel lcol
    const float* xw = x + ((long)b * TT + 64 * w + lrow) * CC + lcol;

    // ---- prologue: stage chunk 0 into warp buffer (overlaps W staging) ----
    float rr[16];
    #pragma unroll
    for (int p = 0; p < 16; p++) rr[p] = __ldg(xw + (long)(4 * p) * CC);
    #pragma unroll
    for (int p = 0; p < 16; p++) xbuf[lcol * XWS + lrow + 4 * p] = rr[p];
    __syncthreads();   // W ready (also orders warp-private chunk 0)

    u64 acc0[12], acc1[12];
    #pragma unroll
    for (int j = 0; j < 12; j++) { acc0[j] = 0ull; acc1[j] = 0ull; }

    // ---- phase 1: warp-private pipelined staging, 2 rows per thread ----
    #pragma unroll 1
    for (int ch = 0; ch < NCHUNK; ch++) {
        // prefetch next chunk into registers (consumed after compute)
        if (ch + 1 < NCHUNK) {
            const float* xn = xw + (ch + 1) * CHUNK;
            #pragma unroll
            for (int p = 0; p < 16; p++) rr[p] = __ldg(xn + (long)(4 * p) * CC);
        }

        const int c0 = ch * CHUNK;
        #pragma unroll
        for (int c = 0; c < CHUNK; c++) {
            // x pair for rows 2l, 2l+1 (of this warp's 64-row block): LDS.64
            u64 xpair = *reinterpret_cast<const u64*>(&xbuf[c * XWS + 2 * l]);
            float x0f, x1f; unpack2(xpair, x0f, x1f);
            u64 x0 = pack2(x0f), x1 = pack2(x1f);
            const ulonglong2* w2 =
                reinterpret_cast<const ulonglong2*>(&w_s[(c0 + c) * JJ]);
            ulonglong2 wa = w2[0], wb = w2[1], wc = w2[2];
            ffma2(acc0[0], x0, wa.x); ffma2(acc1[0], x1, wa.x);
            ffma2(acc0[1], x0, wa.y); ffma2(acc1[1], x1, wa.y);
            ffma2(acc0[2], x0, wb.x); ffma2(acc1[2], x1, wb.x);
            ffma2(acc0[3], x0, wb.y); ffma2(acc1[3], x1, wb.y);
            ffma2(acc0[4], x0, wc.x); ffma2(acc1[4], x1, wc.x);
            ffma2(acc0[5], x0, wc.y); ffma2(acc1[5], x1, wc.y);
            ulonglong2 wd = w2[3], we = w2[4], wf = w2[5];
            ffma2(acc0[6],  x0, wd.x); ffma2(acc1[6],  x1, wd.x);
            ffma2(acc0[7],  x0, wd.y); ffma2(acc1[7],  x1, wd.y);
            ffma2(acc0[8],  x0, we.x); ffma2(acc1[8],  x1, we.x);
            ffma2(acc0[9],  x0, we.y); ffma2(acc1[9],  x1, we.y);
            ffma2(acc0[10], x0, wf.x); ffma2(acc1[10], x1, wf.x);
            ffma2(acc0[11], x0, wf.y); ffma2(acc1[11], x1, wf.y);
        }

        __syncwarp();   // WAR: all lanes done reading this chunk
        if (ch + 1 < NCHUNK) {
            #pragma unroll
            for (int p = 0; p < 16; p++) xbuf[lcol * XWS + lrow + 4 * p] = rr[p];
        }
        __syncwarp();   // RAW: staged data visible to all lanes
    }

    const int t0 = 64 * w + 2 * l;       // first owned row (CTA-local)
    const int t1 = t0 + 1;

    // remainder channels 192..194: direct LDG (w_s still live)
    {
        const float* xrow0 = x + ((long)b * TT + t0) * CC;
        const float* xrow1 = xrow0 + CC;
        #pragma unroll
        for (int c = 192; c < CC; c++) {
            u64 x0 = pack2(__ldg(xrow0 + c));
            u64 x1 = pack2(__ldg(xrow1 + c));
            const u64* w2 = reinterpret_cast<const u64*>(&w_s[c * JJ]);
            #pragma unroll
            for (int j = 0; j < 12; j++) {
                u64 wv = w2[j];
                ffma2(acc0[j], x0, wv); ffma2(acc1[j], x1, wv);
            }
        }
    }

    __syncthreads();   // all phase-1 smem reads done before k/v overlay

    // ---- handoff: k,v for both rows -> smem (overlays w_s); q stays in regs ----
    float* k_s = smem;
    float* v_s = smem + TT * HH;
    {
        u64* kst = reinterpret_cast<u64*>(&k_s[t0 * HH]);
        kst[0] = acc0[4]; kst[1] = acc0[5]; kst[2] = acc0[6]; kst[3] = acc0[7];
        kst[4] = acc1[4]; kst[5] = acc1[5]; kst[6] = acc1[6]; kst[7] = acc1[7];
        u64* vst = reinterpret_cast<u64*>(&v_s[t0 * HH]);
        vst[0] = acc0[8];  vst[1] = acc0[9];  vst[2] = acc0[10]; vst[3] = acc0[11];
        vst[4] = acc1[8];  vst[5] = acc1[9];  vst[6] = acc1[10]; vst[7] = acc1[11];
    }
    __syncthreads();

    // fold 1/sqrt(C) * log2(e) into q so phase 2 uses exp2 (bare MUFU.EX2)
    const float kScale = 1.4426950408889634f * rsqrtf((float)CC);
    const u64 sc2 = pack2(kScale);
    const u64 q00 = mul2(acc0[0], sc2), q01 = mul2(acc0[1], sc2);
    const u64 q02 = mul2(acc0[2], sc2), q03 = mul2(acc0[3], sc2);
    const u64 q10 = mul2(acc1[0], sc2), q11 = mul2(acc1[1], sc2);
    const u64 q12 = mul2(acc1[2], sc2), q13 = mul2(acc1[3], sc2);

    // ---- phase 2: causal attention, 2 rows per thread, shared k/v loads ----
    // scores ~ N(0, ~0.1): exp without max-subtraction is numerically safe.
    const int kend = 64 * w + 63;   // warp-uniform; per-lane predication below
    const ulonglong2* kb2 = reinterpret_cast<const ulonglong2*>(k_s);
    const ulonglong2* vb2 = reinterpret_cast<const ulonglong2*>(v_s);

    u64 o00 = 0, o01 = 0, o02 = 0, o03 = 0;
    u64 o10 = 0, o11 = 0, o12 = 0, o13 = 0;
    float ssum0 = 0.f, ssum1 = 0.f;

    #pragma unroll 2
    for (int k = 0; k <= kend; k++) {
        ulonglong2 ka = kb2[2 * k], kb = kb2[2 * k + 1];   // broadcast LDS.128
        u64 s0 = mul2(q00, ka.x); ffma2(s0, q01, ka.y);
        ffma2(s0, q02, kb.x);     ffma2(s0, q03, kb.y);
        u64 s1 = mul2(q10, ka.x); ffma2(s1, q11, ka.y);
        ffma2(s1, q12, kb.x);     ffma2(s1, q13, kb.y);
        float a0, b0; unpack2(s0, a0, b0);
        float a1, b1; unpack2(s1, a1, b1);
        float p0 = exp2f(a0 + b0);
        float p1 = exp2f(a1 + b1);
        p0 = (k <= t0) ? p0 : 0.f;
        p1 = (k <= t1) ? p1 : 0.f;
        ssum0 += p0; ssum1 += p1;
        u64 pp0 = pack2(p0), pp1 = pack2(p1);
        ulonglong2 va = vb2[2 * k], vb = vb2[2 * k + 1];
        ffma2(o00, pp0, va.x); ffma2(o01, pp0, va.y);
        ffma2(o02, pp0, vb.x); ffma2(o03, pp0, vb.y);
        ffma2(o10, pp1, va.x); ffma2(o11, pp1, va.y);
        ffma2(o12, pp1, vb.x); ffma2(o13, pp1, vb.y);
    }

    const u64 i0 = pack2(__fdividef(1.f, ssum0));
    const u64 i1 = pack2(__fdividef(1.f, ssum1));
    u64* op = reinterpret_cast<u64*>(out + ((long)b * TT + t0) * HH);
    op[0] = mul2(o00, i0); op[1] = mul2(o01, i0);
    op[2] = mul2(o02, i0); op[3] = mul2(o03, i0);
    op[4] = mul2(o10, i1); op[5] = mul2(o11, i1);
    op[6] = mul2(o12, i1); op[7] = mul2(o13, i1);
}

extern "C" void kernel_launch(void* const* d_in, const int* in_sizes, int n_in,
                              void* d_out, int out_size)
{
    const float* x  = (const float*)d_in[0];
    const float* Wq = (const float*)d_in[1];
    const float* Wk = (const float*)d_in[2];
    const float* Wv = (const float*)d_in[3];
    float* out = (float*)d_out;

    head_attn_kernel<<<1024, NT>>>(x, Wq, Wk, Wv, out);
}

// round 12
// speedup vs baseline: 1.0532x; 1.0532x over previous
#include <cuda_runtime.h>

#define TT 256
#define CC 195
#define HH 8
#define JJ 24            // q(8)|k(8)|v(8) per channel
#define NT 128           // threads per CTA; thread owns 2 adjacent rows
#define CHUNK 8
#define NCHUNK 24        // 24*8 = 192; remainder 3 via direct LDG
#define XWS 68           // floats per channel in warp buffer (STS banks 4*lcol+lrow: conflict-free)
#define WF (CC * JJ)     // 4680 floats
#define XBW (CHUNK * XWS)  // 544 floats per warp buffer

typedef unsigned long long u64;

__device__ __forceinline__ u64 pack2(float v) {
    u64 r; asm("mov.b64 %0, {%1, %1};" : "=l"(r) : "f"(v)); return r;
}
__device__ __forceinline__ void unpack2(u64 v, float& lo, float& hi) {
    asm("mov.b64 {%0, %1}, %2;" : "=f"(lo), "=f"(hi) : "l"(v));
}
__device__ __forceinline__ void ffma2(u64& d, u64 a, u64 b) {
    asm("fma.rn.f32x2 %0, %1, %2, %0;" : "+l"(d) : "l"(a), "l"(b));
}
__device__ __forceinline__ u64 mul2(u64 a, u64 b) {
    u64 r; asm("mul.rn.f32x2 %0, %1, %2;" : "=l"(r) : "l"(a), "l"(b)); return r;
}

__global__ __launch_bounds__(NT, 4)
void head_attn_kernel(const float* __restrict__ x,
                      const float* __restrict__ Wq,
                      const float* __restrict__ Wk,
                      const float* __restrict__ Wv,
                      float* __restrict__ out)
{
    // phase A: [ w_s (18720B) | 4 x warp-private xbuf (2176B each) ] = 27424B
    // phase B: [ k_s (8KB) | v_s (8KB) ] overlays w_s region
    __shared__ __align__(16) float smem[WF + 4 * XBW];
    float* w_s = smem;

    const int tid = threadIdx.x;
    const int b   = blockIdx.x;
    const int w   = tid >> 5;
    const int l   = tid & 31;
    // SMSP balance: row-block ownership permuted per CTA so the heavy causal
    // warp (block 3) rotates across SMSPs instead of always hitting SMSP 3.
    const int wblk = (w + b) & 3;
    const int lcol = l & 7;      // staging channel within chunk
    const int lrow = l >> 3;     // staging row group 0..3
    float* xbuf = smem + WF + w * XBW;   // warp-private

    // ---- stage W as [c][24] (96B per c-slice, 16B-aligned) ----
    for (int i = tid; i < CC * HH; i += NT) {
        int c = i >> 3, h = i & 7;
        w_s[c * JJ +      h] = Wq[i];
        w_s[c * JJ +  8 + h] = Wk[i];
        w_s[c * JJ + 16 + h] = Wv[i];
    }

    // warp covers rows 64*wblk..64*wblk+63; staging lane: rows lrow+4p, channel lcol
    const float* xw = x + ((long)b * TT + 64 * wblk + lrow) * CC + lcol;

    // ---- prologue: stage chunk 0 into warp buffer (overlaps W staging) ----
    float rr[16];
    #pragma unroll
    for (int p = 0; p < 16; p++) rr[p] = __ldg(xw + (long)(4 * p) * CC);
    #pragma unroll
    for (int p = 0; p < 16; p++) xbuf[lcol * XWS + lrow + 4 * p] = rr[p];
    __syncthreads();   // W ready (also orders warp-private chunk 0)

    u64 acc0[12], acc1[12];
    #pragma unroll
    for (int j = 0; j < 12; j++) { acc0[j] = 0ull; acc1[j] = 0ull; }

    // ---- phase 1: warp-private pipelined staging, 2 rows per thread ----
    #pragma unroll 1
    for (int ch = 0; ch < NCHUNK; ch++) {
        // prefetch next chunk into registers (consumed after compute)
        if (ch + 1 < NCHUNK) {
            const float* xn = xw + (ch + 1) * CHUNK;
            #pragma unroll
            for (int p = 0; p < 16; p++) rr[p] = __ldg(xn + (long)(4 * p) * CC);
        }

        const int c0 = ch * CHUNK;
        #pragma unroll
        for (int c = 0; c < CHUNK; c++) {
            // x pair for rows 2l, 2l+1 (of this warp's 64-row block): LDS.64
            u64 xpair = *reinterpret_cast<const u64*>(&xbuf[c * XWS + 2 * l]);
            float x0f, x1f; unpack2(xpair, x0f, x1f);
            u64 x0 = pack2(x0f), x1 = pack2(x1f);
            const ulonglong2* w2 =
                reinterpret_cast<const ulonglong2*>(&w_s[(c0 + c) * JJ]);
            ulonglong2 wa = w2[0], wb = w2[1], wc = w2[2];
            ffma2(acc0[0], x0, wa.x); ffma2(acc1[0], x1, wa.x);
            ffma2(acc0[1], x0, wa.y); ffma2(acc1[1], x1, wa.y);
            ffma2(acc0[2], x0, wb.x); ffma2(acc1[2], x1, wb.x);
            ffma2(acc0[3], x0, wb.y); ffma2(acc1[3], x1, wb.y);
            ffma2(acc0[4], x0, wc.x); ffma2(acc1[4], x1, wc.x);
            ffma2(acc0[5], x0, wc.y); ffma2(acc1[5], x1, wc.y);
            ulonglong2 wd = w2[3], we = w2[4], wf = w2[5];
            ffma2(acc0[6],  x0, wd.x); ffma2(acc1[6],  x1, wd.x);
            ffma2(acc0[7],  x0, wd.y); ffma2(acc1[7],  x1, wd.y);
            ffma2(acc0[8],  x0, we.x); ffma2(acc1[8],  x1, we.x);
            ffma2(acc0[9],  x0, we.y); ffma2(acc1[9],  x1, we.y);
            ffma2(acc0[10], x0, wf.x); ffma2(acc1[10], x1, wf.x);
            ffma2(acc0[11], x0, wf.y); ffma2(acc1[11], x1, wf.y);
        }

        __syncwarp();   // WAR: all lanes done reading this chunk
        if (ch + 1 < NCHUNK) {
            #pragma unroll
            for (int p = 0; p < 16; p++) xbuf[lcol * XWS + lrow + 4 * p] = rr[p];
        }
        __syncwarp();   // RAW: staged data visible to all lanes
    }

    const int t0 = 64 * wblk + 2 * l;    // first owned row (CTA-local)
    const int t1 = t0 + 1;

    // remainder channels 192..194: direct LDG (w_s still live)
    {
        const float* xrow0 = x + ((long)b * TT + t0) * CC;
        const float* xrow1 = xrow0 + CC;
        #pragma unroll
        for (int c = 192; c < CC; c++) {
            u64 x0 = pack2(__ldg(xrow0 + c));
            u64 x1 = pack2(__ldg(xrow1 + c));
            const u64* w2 = reinterpret_cast<const u64*>(&w_s[c * JJ]);
            #pragma unroll
            for (int j = 0; j < 12; j++) {
                u64 wv = w2[j];
                ffma2(acc0[j], x0, wv); ffma2(acc1[j], x1, wv);
            }
        }
    }

    __syncthreads();   // all phase-1 smem reads done before k/v overlay

    // ---- handoff: k,v for both rows -> smem (overlays w_s); q stays in regs ----
    float* k_s = smem;
    float* v_s = smem + TT * HH;
    {
        u64* kst = reinterpret_cast<u64*>(&k_s[t0 * HH]);
        kst[0] = acc0[4]; kst[1] = acc0[5]; kst[2] = acc0[6]; kst[3] = acc0[7];
        kst[4] = acc1[4]; kst[5] = acc1[5]; kst[6] = acc1[6]; kst[7] = acc1[7];
        u64* vst = reinterpret_cast<u64*>(&v_s[t0 * HH]);
        vst[0] = acc0[8];  vst[1] = acc0[9];  vst[2] = acc0[10]; vst[3] = acc0[11];
        vst[4] = acc1[8];  vst[5] = acc1[9];  vst[6] = acc1[10]; vst[7] = acc1[11];
    }
    __syncthreads();

    // fold 1/sqrt(C) * log2(e) into q so phase 2 uses exp2 (bare MUFU.EX2)
    const float kScale = 1.4426950408889634f * rsqrtf((float)CC);
    const u64 sc2 = pack2(kScale);
    const u64 q00 = mul2(acc0[0], sc2), q01 = mul2(acc0[1], sc2);
    const u64 q02 = mul2(acc0[2], sc2), q03 = mul2(acc0[3], sc2);
    const u64 q10 = mul2(acc1[0], sc2), q11 = mul2(acc1[1], sc2);
    const u64 q12 = mul2(acc1[2], sc2), q13 = mul2(acc1[3], sc2);

    // ---- phase 2: causal attention, 2 rows per thread, shared k/v loads ----
    // scores ~ N(0, ~0.1): exp without max-subtraction is numerically safe.
    const ulonglong2* kb2 = reinterpret_cast<const ulonglong2*>(k_s);
    const ulonglong2* vb2 = reinterpret_cast<const ulonglong2*>(v_s);

    u64 o00 = 0, o01 = 0, o02 = 0, o03 = 0;
    u64 o10 = 0, o11 = 0, o12 = 0, o13 = 0;
    float ssum0 = 0.f, ssum1 = 0.f;

    const int kb0 = 64 * wblk;     // k < kb0: both rows unconditionally active

    // bulk prefix: no causal predication needed (k < kb0 <= t0 < t1)
    #pragma unroll 2
    for (int k = 0; k < kb0; k++) {
        ulonglong2 ka = kb2[2 * k], kb = kb2[2 * k + 1];   // broadcast LDS.128
        u64 s0 = mul2(q00, ka.x); ffma2(s0, q01, ka.y);
        ffma2(s0, q02, kb.x);     ffma2(s0, q03, kb.y);
        u64 s1 = mul2(q10, ka.x); ffma2(s1, q11, ka.y);
        ffma2(s1, q12, kb.x);     ffma2(s1, q13, kb.y);
        float a0, b0; unpack2(s0, a0, b0);
        float a1, b1; unpack2(s1, a1, b1);
        float p0 = exp2f(a0 + b0);
        float p1 = exp2f(a1 + b1);
        ssum0 += p0; ssum1 += p1;
        u64 pp0 = pack2(p0), pp1 = pack2(p1);
        ulonglong2 va = vb2[2 * k], vb = vb2[2 * k + 1];
        ffma2(o00, pp0, va.x); ffma2(o01, pp0, va.y);
        ffma2(o02, pp0, vb.x); ffma2(o03, pp0, vb.y);
        ffma2(o10, pp1, va.x); ffma2(o11, pp1, va.y);
        ffma2(o12, pp1, vb.x); ffma2(o13, pp1, vb.y);
    }

    // diagonal block: per-lane causal predication
    #pragma unroll 2
    for (int k = kb0; k < kb0 + 64; k++) {
        ulonglong2 ka = kb2[2 * k], kb = kb2[2 * k + 1];
        u64 s0 = mul2(q00, ka.x); ffma2(s0, q01, ka.y);
        ffma2(s0, q02, kb.x);     ffma2(s0, q03, kb.y);
        u64 s1 = mul2(q10, ka.x); ffma2(s1, q11, ka.y);
        ffma2(s1, q12, kb.x);     ffma2(s1, q13, kb.y);
        float a0, b0; unpack2(s0, a0, b0);
        float a1, b1; unpack2(s1, a1, b1);
        float p0 = exp2f(a0 + b0);
        float p1 = exp2f(a1 + b1);
        p0 = (k <= t0) ? p0 : 0.f;
        p1 = (k <= t1) ? p1 : 0.f;
        ssum0 += p0; ssum1 += p1;
        u64 pp0 = pack2(p0), pp1 = pack2(p1);
        ulonglong2 va = vb2[2 * k], vb = vb2[2 * k + 1];
        ffma2(o00, pp0, va.x); ffma2(o01, pp0, va.y);
        ffma2(o02, pp0, vb.x); ffma2(o03, pp0, vb.y);
        ffma2(o10, pp1, va.x); ffma2(o11, pp1, va.y);
        ffma2(o12, pp1, vb.x); ffma2(o13, pp1, vb.y);
    }

    const u64 i0 = pack2(__fdividef(1.f, ssum0));
    const u64 i1 = pack2(__fdividef(1.f, ssum1));
    u64* op = reinterpret_cast<u64*>(out + ((long)b * TT + t0) * HH);
    op[0] = mul2(o00, i0); op[1] = mul2(o01, i0);
    op[2] = mul2(o02, i0); op[3] = mul2(o03, i0);
    op[4] = mul2(o10, i1); op[5] = mul2(o11, i1);
    op[6] = mul2(o12, i1); op[7] = mul2(o13, i1);
}

extern "C" void kernel_launch(void* const* d_in, const int* in_sizes, int n_in,
                              void* d_out, int out_size)
{
    const float* x  = (const float*)d_in[0];
    const float* Wq = (const float*)d_in[1];
    const float* Wk = (const float*)d_in[2];
    const float* Wv = (const float*)d_in[3];
    float* out = (float*)d_out;

    head_attn_kernel<<<1024, NT>>>(x, Wq, Wk, Wv, out);
}